// round 1
// baseline (speedup 1.0000x reference)
#include <cuda_runtime.h>
#include <cstdint>

// Haar wavelet transform, 14 levels, rows of 16384 fp32.
// Reference per level: cA = (even - odd) * INV_SQRT2 ; cD = (even + odd) * INV_SQRT2
// Output = concat over levels k=0..13 of cA_k (shape [nrows, 16384>>(k+1)]),
// then final cD (shape [nrows, 1]).

#define ROW_LEN 16384
#define THREADS 1024

__global__ __launch_bounds__(THREADS, 2)
void haar14_kernel(const float* __restrict__ in, float* __restrict__ out, int nrows)
{
    __shared__ float sm[THREADS];

    const int row = blockIdx.x;
    const int t   = threadIdx.x;
    const float S = 0.70710678118654752440f;

    const float* rowp = in + (size_t)row * ROW_LEN;

    // ---- load 16 contiguous floats per thread (4x LDG.128) ----
    float v[16];
    {
        const float4* p4 = (const float4*)(rowp + t * 16);
        #pragma unroll
        for (int i = 0; i < 4; i++) {
            float4 f = p4[i];
            v[4*i+0] = f.x; v[4*i+1] = f.y; v[4*i+2] = f.z; v[4*i+3] = f.w;
        }
    }

    // Segment base for level k (element offset in out):
    //   base_k = nrows * (16384 - (16384 >> k))
    const size_t NR = (size_t)nrows;

    // ---- level 0: out length 8192 per row ----
    float d[8];
    {
        float a[8];
        #pragma unroll
        for (int i = 0; i < 8; i++) {
            float e = v[2*i], o = v[2*i+1];
            a[i] = (e - o) * S;
            d[i] = (e + o) * S;
        }
        float4* o4 = (float4*)(out + NR * (size_t)0 + (size_t)row * 8192 + t * 8);
        o4[0] = make_float4(a[0], a[1], a[2], a[3]);
        o4[1] = make_float4(a[4], a[5], a[6], a[7]);
    }

    // ---- level 1: out length 4096 ----
    {
        float a[4];
        #pragma unroll
        for (int i = 0; i < 4; i++) {
            float e = d[2*i], o = d[2*i+1];
            a[i] = (e - o) * S;
            d[i] = (e + o) * S;   // write idx i <= read idx 2i: safe in-place
        }
        size_t base = NR * (size_t)(16384 - (16384 >> 1));
        float4* o4 = (float4*)(out + base + (size_t)row * 4096 + t * 4);
        o4[0] = make_float4(a[0], a[1], a[2], a[3]);
    }

    // ---- level 2: out length 2048 ----
    {
        float a[2];
        #pragma unroll
        for (int i = 0; i < 2; i++) {
            float e = d[2*i], o = d[2*i+1];
            a[i] = (e - o) * S;
            d[i] = (e + o) * S;
        }
        size_t base = NR * (size_t)(16384 - (16384 >> 2));
        float2* o2 = (float2*)(out + base + (size_t)row * 2048 + t * 2);
        o2[0] = make_float2(a[0], a[1]);
    }

    // ---- level 3: out length 1024 ----
    float dres;
    {
        float e = d[0], o = d[1];
        float a = (e - o) * S;
        dres    = (e + o) * S;
        size_t base = NR * (size_t)(16384 - (16384 >> 3));
        out[base + (size_t)row * 1024 + t] = a;
    }

    // ---- cooperative levels 4..13 through shared memory ----
    sm[t] = dres;
    __syncthreads();

    int n = THREADS;   // current cD length
    int k = 4;         // level index
    while (n > 1) {
        int m = n >> 1;
        float dd = 0.0f;
        if (t < m) {
            float e = sm[2*t], o = sm[2*t+1];
            float a = (e - o) * S;
            dd      = (e + o) * S;
            size_t base = NR * (size_t)(16384 - (16384 >> k));
            out[base + (size_t)row * m + t] = a;
        }
        __syncthreads();
        if (t < m) sm[t] = dd;
        __syncthreads();
        n = m;
        ++k;
    }

    // ---- final cD (length 1), segment 14 ----
    if (t == 0) {
        out[NR * (size_t)16383 + row] = sm[0];
    }
}

extern "C" void kernel_launch(void* const* d_in, const int* in_sizes, int n_in,
                              void* d_out, int out_size)
{
    const float* x = (const float*)d_in[0];
    float* out = (float*)d_out;
    int n = in_sizes[0];
    int nrows = n / ROW_LEN;   // 4096 for (64,64,16384)
    haar14_kernel<<<nrows, THREADS>>>(x, out, nrows);
}